// round 7
// baseline (speedup 1.0000x reference)
#include <cuda_runtime.h>
#include <cuda_bf16.h>
#include <cstdint>

// Capsule routing: B=2048, R=64, H=512, NUM_ITER=3.  Output final_vec [B,H] f32.
//
// R7: software-pipelined persistent kernel. 148 CTAs x 512 threads, thread =
// one full h-column (xr[64] in regs). Per batch only TWO CTA barriers:
//   softmax1(i)  [MUFU-paced; hides LDS stats-stream of batch i+1]
//   B1: norm reduction
//   softmax2(i)  [MUFU-paced; hides LDS reload of batch i+1 into xr in-place]
//   B2: merged reduction (norm2(i) + norm0(i+1)) + TMA ring refill
// TMA 7-slot x 32KB chunk ring. absmax replaces max/min (m = |wl|*absmax).

#define B_DIM 2048
#define R_DIM 64
#define H_DIM 512
#define NT 512
#define GRID 148
#define NSLOT 7
#define CHUNK_ROWS 16
#define CHUNK_FLOATS (CHUNK_ROWS * H_DIM)      // 8192
#define CHUNK_BYTES  (CHUNK_FLOATS * 4)        // 32768

__device__ __forceinline__ float fast_exp2(float x) {
    float r;
    asm("ex2.approx.ftz.f32 %0, %1;" : "=f"(r) : "f"(x));
    return r;
}

__device__ __forceinline__ void mbar_wait_acq(uint32_t mbar, uint32_t parity) {
    asm volatile(
        "{\n\t"
        ".reg .pred P;\n\t"
        "WAIT_LOOP_%=:\n\t"
        "mbarrier.try_wait.parity.acquire.cta.shared::cta.b64 P, [%0], %1, 0x989680;\n\t"
        "@P bra.uni WAIT_DONE_%=;\n\t"
        "bra.uni WAIT_LOOP_%=;\n\t"
        "WAIT_DONE_%=:\n\t"
        "}"
        :: "r"(mbar), "r"(parity) : "memory");
}

// Warp-level sum -> write one value per warp into sred[wid].
__device__ __forceinline__ void warp_part(float val, volatile float* sred,
                                          int wid, int lid) {
    #pragma unroll
    for (int o = 16; o > 0; o >>= 1)
        val += __shfl_xor_sync(0xffffffffu, val, o);
    if (lid == 0) sred[wid] = val;
}

// After __syncthreads(): combine the 16 partials (all threads get result).
__device__ __forceinline__ float final_sum(volatile float* sred, int lid) {
    float v = sred[lid & 15];
    #pragma unroll
    for (int o = 8; o > 0; o >>= 1)
        v += __shfl_xor_sync(0xffffffffu, v, o);
    return v;
}

__global__ void __launch_bounds__(NT, 1)
capsule_kernel(const float* __restrict__ x, float* __restrict__ out) {
    extern __shared__ float sbuf[];            // NSLOT * 32KB = 224KB ring
    __shared__ float sred0[16], sred1[16], sred2[16], sred3[16];
    __shared__ uint64_t mbars[NSLOT];

    const uint32_t mbar0 = (uint32_t)__cvta_generic_to_shared(mbars);
    const uint32_t sbuf_addr = (uint32_t)__cvta_generic_to_shared(sbuf);

    const int tid = threadIdx.x;               // == h column
    const int bid = blockIdx.x;
    const int wid = tid >> 5;
    const int lid = tid & 31;

    if (tid < NSLOT)
        asm volatile("mbarrier.init.shared.b64 [%0], %1;"
                     :: "r"(mbar0 + 8u * tid), "r"(1));
    asm volatile("fence.proxy.async.shared::cta;" ::: "memory");
    __syncthreads();

    const int nbat = (B_DIM - bid + GRID - 1) / GRID;
    const int total_chunks = 4 * nbat;

    // ---- TMA chunk issue (thread 0 only) ----
    auto issue = [&](int g) {
        int slot = g % NSLOT;
        int gb = bid + (g >> 2) * GRID;
        const char* src = (const char*)(x + (size_t)gb * (R_DIM * H_DIM)
                                          + (size_t)(g & 3) * CHUNK_FLOATS);
        uint32_t mb = mbar0 + 8u * slot;
        asm volatile("mbarrier.arrive.expect_tx.shared.b64 _, [%0], %1;"
                     :: "r"(mb), "r"(CHUNK_BYTES));
        asm volatile(
            "cp.async.bulk.shared::cta.global.mbarrier::complete_tx::bytes "
            "[%0], [%1], %2, [%3];"
            :: "r"(sbuf_addr + (uint32_t)slot * CHUNK_BYTES), "l"(src),
               "r"(CHUNK_BYTES), "r"(mb) : "memory");
    };

    int cursor = 0;
    if (tid == 0) {
        int lim = total_chunks < NSLOT ? total_chunks : NSLOT;
        for (; cursor < lim; cursor++) issue(cursor);
    }

    const float L2E = 1.4426950408889634f;

    // ================= prologue: batch 0 =================
    #pragma unroll
    for (int c = 0; c < 4; c++)
        mbar_wait_acq(mbar0 + 8u * c, 0u);

    float xr[R_DIM];
    float sum0 = 0.0f, absmax = 0.0f;
    #pragma unroll
    for (int c = 0; c < 4; c++) {
        const float* cp = sbuf + (size_t)c * CHUNK_FLOATS + tid;
        #pragma unroll
        for (int r = 0; r < CHUNK_ROWS; r++) {
            float xv = cp[r * H_DIM];
            xr[c * CHUNK_ROWS + r] = xv;
            sum0 += xv;
            absmax = fmaxf(absmax, fabsf(xv));
        }
    }
    float s = sum0 * (1.0f / (float)R_DIM);
    warp_part(s * s, sred0, wid, lid);
    __syncthreads();                           // prologue barrier (batch0 consumed)
    if (tid == 0) {                            // chunks 7..10 now slot-safe
        int lim = total_chunks - 1 < 10 ? total_chunks - 1 : 10;
        for (; cursor <= lim; cursor++) issue(cursor);
    }
    {
        float norm = final_sum(sred0, lid);
        float sq = sqrtf(norm);
        float f  = sq / (1.0f + sq);
        s = f * s;                              // v1 component
    }
    float w = s;                                // routing weight accumulator

    // ================= steady loop =================
    for (int i = 0; i < nbat; i++) {
        const int b = bid + i * GRID;
        const bool hn = (i + 1 < nbat);

        // wait next batch's chunks (all threads; acquire for later LDS)
        if (hn) {
            #pragma unroll
            for (int c = 0; c < 4; c++) {
                int g = 4 * (i + 1) + c;
                mbar_wait_acq(mbar0 + 8u * (g % NSLOT),
                              (uint32_t)((g / NSLOT) & 1));
            }
        }
        // next-batch chunk base pointers (clamped when no next batch)
        const float* np[4];
        #pragma unroll
        for (int c = 0; c < 4; c++) {
            int g = 4 * (i + 1) + c;
            if (g > total_chunks - 1) g = total_chunks - 1;
            np[c] = sbuf + (size_t)(g % NSLOT) * CHUNK_FLOATS + tid;
        }

        // ---- softmax1(i), hiding stats-stream of batch i+1 ----
        float wl = w * L2E;
        float m  = fabsf(wl) * absmax;
        float se = 0.0f, sex = 0.0f;
        float nsum = 0.0f, namax = 0.0f;
        #pragma unroll
        for (int r = 0; r < R_DIM; r++) {
            float e = fast_exp2(fmaf(xr[r], wl, -m));
            se += e;
            sex = fmaf(e, xr[r], sex);
            float xv = np[r >> 4][(r & 15) * H_DIM];
            nsum += xv;
            namax = fmaxf(namax, fabsf(xv));
        }
        s = sex / se;

        // ---- B1: norm of iter1 ----
        warp_part(s * s, sred1, wid, lid);
        __syncthreads();
        {
            float norm = final_sum(sred1, lid);
            float sq = sqrtf(norm);
            float f  = sq / (1.0f + sq);
            w += f * s;
        }

        // ---- softmax2(i), reloading xr with batch i+1 in place ----
        wl = w * L2E;
        m  = fabsf(wl) * absmax;
        float se2 = 0.0f, sex2 = 0.0f;
        #pragma unroll
        for (int r = 0; r < R_DIM; r++) {
            float xo = xr[r];
            float e = fast_exp2(fmaf(xo, wl, -m));
            se2 += e;
            sex2 = fmaf(e, xo, sex2);
            xr[r] = np[r >> 4][(r & 15) * H_DIM];   // 2nd read; overwrites dead xo
        }
        float s2 = sex2 / se2;
        float s0 = nsum * (1.0f / (float)R_DIM);

        // ---- B2: merged reductions (norm2(i), norm0(i+1)) + refill ----
        warp_part(s2 * s2, sred2, wid, lid);
        warp_part(s0 * s0, sred3, wid, lid);
        __syncthreads();
        if (tid == 0) {                        // batch i+1 fully consumed now
            int lim = 4 * i + 14;
            if (lim > total_chunks - 1) lim = total_chunks - 1;
            for (; cursor <= lim; cursor++) issue(cursor);
        }
        {
            float norm2 = final_sum(sred2, lid);
            float sq2 = sqrtf(norm2);
            float f2  = sq2 / (1.0f + sq2);
            out[(size_t)b * H_DIM + tid] = f2 * s2;
        }
        if (hn) {
            float norm0 = final_sum(sred3, lid);
            float sq0 = sqrtf(norm0);
            float f0  = sq0 / (1.0f + sq0);
            w = f0 * s0;                       // w1 of batch i+1
            absmax = namax;
        }
    }
}

extern "C" void kernel_launch(void* const* d_in, const int* in_sizes, int n_in,
                              void* d_out, int out_size) {
    const float* x = (const float*)d_in[0];
    float* out = (float*)d_out;
    cudaFuncSetAttribute(capsule_kernel,
                         cudaFuncAttributeMaxDynamicSharedMemorySize,
                         NSLOT * CHUNK_BYTES);
    capsule_kernel<<<GRID, NT, NSLOT * CHUNK_BYTES>>>(x, out);
}

// round 8
// speedup vs baseline: 1.1514x; 1.1514x over previous
#include <cuda_runtime.h>
#include <cuda_bf16.h>
#include <cstdint>

// Capsule routing: B=2048, R=64, H=512, NUM_ITER=3.  Output final_vec [B,H] f32.
//
// R8 = R6 + corrected software pipeline (fixes R7's bugs):
//  - softmax1(i) is PURE MUFU (no LDS interleave, no prior wait on i+1).
//  - elected waits for batch i+1 sit AFTER softmax1, folded into barrier B1.
//  - softmax2(i) reloads xr in place from batch i+1 and computes its
//    sum/absmax (hidden under MUFU pacing).
//  - B2 merges norm2(i) + norm0(i+1) reductions and the TMA ring refill.
// 2 CTA barriers per batch; standalone LDS pass eliminated in steady state.
// 148 persistent CTAs x 512 threads, thread = full h-column (xr[64]).
// TMA 7-slot x 32KB chunk ring (224KB smem).

#define B_DIM 2048
#define R_DIM 64
#define H_DIM 512
#define NT 512
#define GRID 148
#define NSLOT 7
#define CHUNK_ROWS 16
#define CHUNK_FLOATS (CHUNK_ROWS * H_DIM)      // 8192
#define CHUNK_BYTES  (CHUNK_FLOATS * 4)        // 32768

__device__ __forceinline__ float fast_exp2(float x) {
    float r;
    asm("ex2.approx.ftz.f32 %0, %1;" : "=f"(r) : "f"(x));
    return r;
}

__device__ __forceinline__ void mbar_wait_acq(uint32_t mbar, uint32_t parity) {
    asm volatile(
        "{\n\t"
        ".reg .pred P;\n\t"
        "WAIT_LOOP_%=:\n\t"
        "mbarrier.try_wait.parity.acquire.cta.shared::cta.b64 P, [%0], %1, 0x989680;\n\t"
        "@P bra.uni WAIT_DONE_%=;\n\t"
        "bra.uni WAIT_LOOP_%=;\n\t"
        "WAIT_DONE_%=:\n\t"
        "}"
        :: "r"(mbar), "r"(parity) : "memory");
}

// Warp-level sum -> one value per warp into sred[wid].
__device__ __forceinline__ void warp_part(float val, volatile float* sred,
                                          int wid, int lid) {
    #pragma unroll
    for (int o = 16; o > 0; o >>= 1)
        val += __shfl_xor_sync(0xffffffffu, val, o);
    if (lid == 0) sred[wid] = val;
}

// After __syncthreads(): combine 16 partials (all threads get result).
__device__ __forceinline__ float final_sum(volatile float* sred, int lid) {
    float v = sred[lid & 15];
    #pragma unroll
    for (int o = 8; o > 0; o >>= 1)
        v += __shfl_xor_sync(0xffffffffu, v, o);
    return v;
}

__global__ void __launch_bounds__(NT, 1)
capsule_kernel(const float* __restrict__ x, float* __restrict__ out) {
    extern __shared__ float sbuf[];            // NSLOT * 32KB = 224KB ring
    __shared__ float sred0[16], sred1[16], sred2[16], sred3[16];
    __shared__ uint64_t mbars[NSLOT];

    const uint32_t mbar0 = (uint32_t)__cvta_generic_to_shared(mbars);
    const uint32_t sbuf_addr = (uint32_t)__cvta_generic_to_shared(sbuf);

    const int tid = threadIdx.x;               // == h column
    const int bid = blockIdx.x;
    const int wid = tid >> 5;
    const int lid = tid & 31;

    if (tid < NSLOT)
        asm volatile("mbarrier.init.shared.b64 [%0], %1;"
                     :: "r"(mbar0 + 8u * tid), "r"(1));
    asm volatile("fence.proxy.async.shared::cta;" ::: "memory");
    __syncthreads();

    const int nbat = (B_DIM - bid + GRID - 1) / GRID;
    const int total_chunks = 4 * nbat;

    auto issue = [&](int g) {
        int slot = g % NSLOT;
        int gb = bid + (g >> 2) * GRID;
        const char* src = (const char*)(x + (size_t)gb * (R_DIM * H_DIM)
                                          + (size_t)(g & 3) * CHUNK_FLOATS);
        uint32_t mb = mbar0 + 8u * slot;
        asm volatile("mbarrier.arrive.expect_tx.shared.b64 _, [%0], %1;"
                     :: "r"(mb), "r"(CHUNK_BYTES));
        asm volatile(
            "cp.async.bulk.shared::cta.global.mbarrier::complete_tx::bytes "
            "[%0], [%1], %2, [%3];"
            :: "r"(sbuf_addr + (uint32_t)slot * CHUNK_BYTES), "l"(src),
               "r"(CHUNK_BYTES), "r"(mb) : "memory");
    };

    int cursor = 0;
    if (tid == 0) {
        int lim = total_chunks < NSLOT ? total_chunks : NSLOT;
        for (; cursor < lim; cursor++) issue(cursor);
    }

    const float L2E = 1.4426950408889634f;

    // ================= prologue: batch 0 =================
    if (tid < 4)
        mbar_wait_acq(mbar0 + 8u * tid, 0u);
    __syncthreads();

    float xr[R_DIM];
    float sum0 = 0.0f, absmax = 0.0f;
    #pragma unroll
    for (int c = 0; c < 4; c++) {
        const float* cp = sbuf + (size_t)c * CHUNK_FLOATS + tid;
        #pragma unroll
        for (int r = 0; r < CHUNK_ROWS; r++) {
            float xv = cp[r * H_DIM];
            xr[c * CHUNK_ROWS + r] = xv;
            sum0 += xv;
            absmax = fmaxf(absmax, fabsf(xv));
        }
    }
    float s0p = sum0 * (1.0f / (float)R_DIM);
    warp_part(s0p * s0p, sred0, wid, lid);
    __syncthreads();                           // batch 0 consumed
    if (tid == 0) {                            // slots for chunks 7..10 free
        int lim = total_chunks - 1 < 10 ? total_chunks - 1 : 10;
        for (; cursor <= lim; cursor++) issue(cursor);
    }
    float w;
    {
        float norm = final_sum(sred0, lid);
        float sq = sqrtf(norm);
        w = (sq / (1.0f + sq)) * s0p;           // v1 of batch 0
    }

    // ================= steady loop =================
    for (int i = 0; i < nbat; i++) {
        const int b = bid + i * GRID;
        const bool hn = (i + 1 < nbat);

        // ---- softmax1(i): pure MUFU ----
        float wl = w * L2E;
        float m  = fabsf(wl) * absmax;
        float se = 0.0f, sex = 0.0f;
        #pragma unroll
        for (int r = 0; r < R_DIM; r++) {
            float e = fast_exp2(fmaf(xr[r], wl, -m));
            se += e;
            sex = fmaf(e, xr[r], sex);
        }
        float s1 = sex / se;

        // elected waits for batch i+1, folded into B1
        if (hn && tid < 4) {
            int g = 4 * (i + 1) + tid;
            mbar_wait_acq(mbar0 + 8u * (g % NSLOT),
                          (uint32_t)((g / NSLOT) & 1));
        }
        warp_part(s1 * s1, sred1, wid, lid);
        __syncthreads();                       // B1
        {
            float norm = final_sum(sred1, lid);
            float sq = sqrtf(norm);
            w += (sq / (1.0f + sq)) * s1;
        }

        // next-batch chunk base pointers (clamped for the last batch)
        const float* np[4];
        #pragma unroll
        for (int c = 0; c < 4; c++) {
            int g = 4 * (i + 1) + c;
            if (g > total_chunks - 1) g = total_chunks - 1;
            np[c] = sbuf + (size_t)(g % NSLOT) * CHUNK_FLOATS + tid;
        }

        // ---- softmax2(i): MUFU + in-place reload of batch i+1 + stats ----
        wl = w * L2E;
        m  = fabsf(wl) * absmax;
        float se2 = 0.0f, sex2 = 0.0f;
        float nsum = 0.0f, namax = 0.0f;
        #pragma unroll
        for (int r = 0; r < R_DIM; r++) {
            float xo = xr[r];
            float e = fast_exp2(fmaf(xo, wl, -m));
            se2 += e;
            sex2 = fmaf(e, xo, sex2);
            float xv = np[r >> 4][(r & 15) * H_DIM];
            xr[r] = xv;                        // xo dead after this r
            nsum += xv;
            namax = fmaxf(namax, fabsf(xv));
        }
        float s2 = sex2 / se2;
        float s0 = nsum * (1.0f / (float)R_DIM);

        // ---- B2: merged reductions + refill ----
        warp_part(s2 * s2, sred2, wid, lid);
        warp_part(s0 * s0, sred3, wid, lid);
        __syncthreads();                       // B2 (batch i+1 consumed into regs)
        if (tid == 0) {
            int lim = 4 * i + 14;              // slots of <= batch i+1 free
            if (lim > total_chunks - 1) lim = total_chunks - 1;
            for (; cursor <= lim; cursor++) issue(cursor);
        }
        {
            float norm2 = final_sum(sred2, lid);
            float sq2 = sqrtf(norm2);
            out[(size_t)b * H_DIM + tid] = (sq2 / (1.0f + sq2)) * s2;
        }
        if (hn) {
            float norm0 = final_sum(sred3, lid);
            float sq0 = sqrtf(norm0);
            w = (sq0 / (1.0f + sq0)) * s0;     // v1 of batch i+1
            absmax = namax;
        }
    }
}

extern "C" void kernel_launch(void* const* d_in, const int* in_sizes, int n_in,
                              void* d_out, int out_size) {
    const float* x = (const float*)d_in[0];
    float* out = (float*)d_out;
    cudaFuncSetAttribute(capsule_kernel,
                         cudaFuncAttributeMaxDynamicSharedMemorySize,
                         NSLOT * CHUNK_BYTES);
    capsule_kernel<<<GRID, NT, NSLOT * CHUNK_BYTES>>>(x, out);
}

// round 11
// speedup vs baseline: 1.1952x; 1.0381x over previous
#include <cuda_runtime.h>
#include <cuda_bf16.h>
#include <cstdint>

// Capsule routing: B=2048, R=64, H=512, NUM_ITER=3.  Output final_vec [B,H] f32.
//
// R10 = R9 structure with shuffle reductions (redux.f32 doesn't exist on
// sm_103 — ptxas verified):
//  - norm2(i) final-combine + output store DEFERRED into softmax1(i+1) window.
//  - __fdividef everywhere on the critical path.
//  - softmax1 pure MUFU; softmax2 interleaves in-place reload of batch i+1
//    plus its sum/absmax stats; B2 merges norm2-partial + norm0(i+1) + refill.
// 148 persistent CTAs x 512 threads, thread = full h-column (xr[64]).
// TMA 7-slot x 32KB chunk ring; 2 CTA barriers per batch.

#define B_DIM 2048
#define R_DIM 64
#define H_DIM 512
#define NT 512
#define GRID 148
#define NSLOT 7
#define CHUNK_ROWS 16
#define CHUNK_FLOATS (CHUNK_ROWS * H_DIM)      // 8192
#define CHUNK_BYTES  (CHUNK_FLOATS * 4)        // 32768

__device__ __forceinline__ float fast_exp2(float x) {
    float r;
    asm("ex2.approx.ftz.f32 %0, %1;" : "=f"(r) : "f"(x));
    return r;
}

__device__ __forceinline__ void mbar_wait_acq(uint32_t mbar, uint32_t parity) {
    asm volatile(
        "{\n\t"
        ".reg .pred P;\n\t"
        "WAIT_LOOP_%=:\n\t"
        "mbarrier.try_wait.parity.acquire.cta.shared::cta.b64 P, [%0], %1, 0x989680;\n\t"
        "@P bra.uni WAIT_DONE_%=;\n\t"
        "bra.uni WAIT_LOOP_%=;\n\t"
        "WAIT_DONE_%=:\n\t"
        "}"
        :: "r"(mbar), "r"(parity) : "memory");
}

// Warp partial sum -> sred[wid] (call before a __syncthreads()).
__device__ __forceinline__ void warp_part(float val, volatile float* sred,
                                          int wid, int lid) {
    #pragma unroll
    for (int o = 16; o > 0; o >>= 1)
        val += __shfl_xor_sync(0xffffffffu, val, o);
    if (lid == 0) sred[wid] = val;
}

// After the barrier: combine the 16 partials (all threads get the result).
__device__ __forceinline__ float final_sum(volatile float* sred, int lid) {
    float v = sred[lid & 15];
    #pragma unroll
    for (int o = 8; o > 0; o >>= 1)
        v += __shfl_xor_sync(0xffffffffu, v, o);
    return v;
}

__global__ void __launch_bounds__(NT, 1)
capsule_kernel(const float* __restrict__ x, float* __restrict__ out) {
    extern __shared__ float sbuf[];            // NSLOT * 32KB = 224KB ring
    __shared__ float sred0[16], sred1[16], sred2[16], sred3[16];
    __shared__ uint64_t mbars[NSLOT];

    const uint32_t mbar0 = (uint32_t)__cvta_generic_to_shared(mbars);
    const uint32_t sbuf_addr = (uint32_t)__cvta_generic_to_shared(sbuf);

    const int tid = threadIdx.x;               // == h column
    const int bid = blockIdx.x;
    const int wid = tid >> 5;
    const int lid = tid & 31;

    if (tid < NSLOT)
        asm volatile("mbarrier.init.shared.b64 [%0], %1;"
                     :: "r"(mbar0 + 8u * tid), "r"(1));
    asm volatile("fence.proxy.async.shared::cta;" ::: "memory");
    __syncthreads();

    const int nbat = (B_DIM - bid + GRID - 1) / GRID;
    const int total_chunks = 4 * nbat;

    auto issue = [&](int g) {
        int slot = g % NSLOT;
        int gb = bid + (g >> 2) * GRID;
        const char* src = (const char*)(x + (size_t)gb * (R_DIM * H_DIM)
                                          + (size_t)(g & 3) * CHUNK_FLOATS);
        uint32_t mb = mbar0 + 8u * slot;
        asm volatile("mbarrier.arrive.expect_tx.shared.b64 _, [%0], %1;"
                     :: "r"(mb), "r"(CHUNK_BYTES));
        asm volatile(
            "cp.async.bulk.shared::cta.global.mbarrier::complete_tx::bytes "
            "[%0], [%1], %2, [%3];"
            :: "r"(sbuf_addr + (uint32_t)slot * CHUNK_BYTES), "l"(src),
               "r"(CHUNK_BYTES), "r"(mb) : "memory");
    };

    int cursor = 0;
    if (tid == 0) {
        int lim = total_chunks < NSLOT ? total_chunks : NSLOT;
        for (; cursor < lim; cursor++) issue(cursor);
    }

    const float L2E = 1.4426950408889634f;

    // ================= prologue: batch 0 =================
    if (tid < 4)
        mbar_wait_acq(mbar0 + 8u * tid, 0u);
    __syncthreads();

    float xr[R_DIM];
    float sum0 = 0.0f, absmax = 0.0f;
    #pragma unroll
    for (int c = 0; c < 4; c++) {
        const float* cp = sbuf + (size_t)c * CHUNK_FLOATS + tid;
        #pragma unroll
        for (int r = 0; r < CHUNK_ROWS; r++) {
            float xv = cp[r * H_DIM];
            xr[c * CHUNK_ROWS + r] = xv;
            sum0 += xv;
            absmax = fmaxf(absmax, fabsf(xv));
        }
    }
    float s0p = sum0 * (1.0f / (float)R_DIM);
    warp_part(s0p * s0p, sred0, wid, lid);
    __syncthreads();                           // batch 0 consumed
    if (tid == 0) {                            // slots for chunks 7..10 free
        int lim = total_chunks - 1 < 10 ? total_chunks - 1 : 10;
        for (; cursor <= lim; cursor++) issue(cursor);
    }
    float w;
    {
        float norm = final_sum(sred0, lid);
        float sq = sqrtf(norm);
        w = __fdividef(sq, 1.0f + sq) * s0p;    // v1 of batch 0
    }

    float s2_prev = 0.0f;                      // deferred output state
    int   b_prev  = -1;

    // ================= steady loop =================
    for (int i = 0; i < nbat; i++) {
        const int b = bid + i * GRID;
        const bool hn = (i + 1 < nbat);

        // ---- softmax1(i): pure MUFU ----
        float wl = w * L2E;
        float m  = fabsf(wl) * absmax;
        float se = 0.0f, sex = 0.0f;
        #pragma unroll
        for (int r = 0; r < R_DIM; r++) {
            float e = fast_exp2(fmaf(xr[r], wl, -m));
            se += e;
            sex = fmaf(e, xr[r], sex);
        }
        float s1 = __fdividef(sex, se);

        // ---- deferred: finish batch i-1's norm2 + output store ----
        // sred2 written before B2(i-1)'s sync; next write is after B1(i)'s
        // sync below -> race-free.
        if (b_prev >= 0) {
            float norm2 = final_sum(sred2, lid);
            float sq2 = sqrtf(norm2);
            out[(size_t)b_prev * H_DIM + tid] =
                __fdividef(sq2, 1.0f + sq2) * s2_prev;
        }

        // elected waits for batch i+1, folded into B1
        if (hn && tid < 4) {
            int g = 4 * (i + 1) + tid;
            mbar_wait_acq(mbar0 + 8u * (g % NSLOT),
                          (uint32_t)((g / NSLOT) & 1));
        }
        warp_part(s1 * s1, sred1, wid, lid);
        __syncthreads();                       // B1
        {
            float norm = final_sum(sred1, lid);
            float sq = sqrtf(norm);
            w += __fdividef(sq, 1.0f + sq) * s1;
        }

        // next-batch chunk base pointers (clamped for the last batch)
        const float* np[4];
        #pragma unroll
        for (int c = 0; c < 4; c++) {
            int g = 4 * (i + 1) + c;
            if (g > total_chunks - 1) g = total_chunks - 1;
            np[c] = sbuf + (size_t)(g % NSLOT) * CHUNK_FLOATS + tid;
        }

        // ---- softmax2(i): MUFU + in-place reload of batch i+1 + stats ----
        wl = w * L2E;
        m  = fabsf(wl) * absmax;
        float se2 = 0.0f, sex2 = 0.0f;
        float nsum = 0.0f, namax = 0.0f;
        #pragma unroll
        for (int r = 0; r < R_DIM; r++) {
            float xo = xr[r];
            float e = fast_exp2(fmaf(xo, wl, -m));
            se2 += e;
            sex2 = fmaf(e, xo, sex2);
            float xv = np[r >> 4][(r & 15) * H_DIM];
            xr[r] = xv;                        // xo dead after this r
            nsum += xv;
            namax = fmaxf(namax, fabsf(xv));
        }
        float s2 = __fdividef(sex2, se2);
        float s0 = nsum * (1.0f / (float)R_DIM);

        // ---- B2: partial reductions + refill ----
        warp_part(s2 * s2, sred2, wid, lid);
        warp_part(s0 * s0, sred3, wid, lid);
        __syncthreads();                       // B2 (batch i+1 consumed)
        if (tid == 0) {
            int lim = 4 * i + 14;              // slots of <= batch i+1 free
            if (lim > total_chunks - 1) lim = total_chunks - 1;
            for (; cursor <= lim; cursor++) issue(cursor);
        }
        if (hn) {
            float norm0 = final_sum(sred3, lid);
            float sq0 = sqrtf(norm0);
            w = __fdividef(sq0, 1.0f + sq0) * s0;   // v1 of batch i+1
            absmax = namax;
        }
        s2_prev = s2;
        b_prev  = b;
    }

    // ---- epilogue: flush last batch's output ----
    {
        float norm2 = final_sum(sred2, lid);
        float sq2 = sqrtf(norm2);
        out[(size_t)b_prev * H_DIM + tid] =
            __fdividef(sq2, 1.0f + sq2) * s2_prev;
    }
}

extern "C" void kernel_launch(void* const* d_in, const int* in_sizes, int n_in,
                              void* d_out, int out_size) {
    const float* x = (const float*)d_in[0];
    float* out = (float*)d_out;
    cudaFuncSetAttribute(capsule_kernel,
                         cudaFuncAttributeMaxDynamicSharedMemorySize,
                         NSLOT * CHUNK_BYTES);
    capsule_kernel<<<GRID, NT, NSLOT * CHUNK_BYTES>>>(x, out);
}